// round 1
// baseline (speedup 1.0000x reference)
#include <cuda_runtime.h>

#define NEG (-1e30f)

constexpr int B = 8, IMG = 224, PP = 16, G = 14;
constexpr int N = 196, PD = 256, D = 128, DFF = 256, C = 1000;
constexpr int BN = B * N;   // 1568 rows

// ---------------- scratch (device globals; no allocation) ----------------
__device__ float g_x[BN * D];      // residual stream
__device__ float g_q[BN * D];
__device__ float g_k[BN * D];
__device__ float g_v[BN * D];
__device__ float g_h1[BN * DFF];
__device__ float g_pooled[B * D];

// ---------------- tropical GEMM core ----------------
// Computes acc[r] (r=0..7 rows) for out-col = colbase + tid, over K = KDIM.
// xs: shared [8][KDIM] input rows. ws: shared staging [64][129] (W transposed).
// W layout: [out_col][KDIM] row-major.
template <int KDIM>
__device__ __forceinline__ void mm_core(const float* xs, float (*ws)[129],
                                        const float* __restrict__ W, int colbase,
                                        float* acc, int tid) {
  for (int k0 = 0; k0 < KDIM; k0 += 64) {
    __syncthreads();
    // stage W chunk transposed: ws[kk][c] = W[(colbase+c)*KDIM + k0 + kk]
    #pragma unroll
    for (int it = 0; it < 64; it++) {
      int idx = it * 128 + tid;
      int c = idx >> 6, kk = idx & 63;           // coalesced global read, conflict-free smem write
      ws[kk][c] = W[(colbase + c) * KDIM + k0 + kk];
    }
    __syncthreads();
    #pragma unroll 4
    for (int kk = 0; kk < 64; kk += 4) {
      float w0 = ws[kk][tid], w1 = ws[kk + 1][tid];
      float w2 = ws[kk + 2][tid], w3 = ws[kk + 3][tid];
      #pragma unroll
      for (int r = 0; r < 8; r++) {
        float4 xv = *reinterpret_cast<const float4*>(xs + r * KDIM + k0 + kk);  // broadcast
        float a = acc[r];
        a = fmaxf(a, xv.x + w0);
        a = fmaxf(a, xv.y + w1);
        a = fmaxf(a, xv.z + w2);
        a = fmaxf(a, xv.w + w3);
        acc[r] = a;
      }
    }
  }
}

// ---------------- embed: patchify + trop_mm(embed_W) + pos ----------------
__global__ void k_embed(const float* __restrict__ x, const float* __restrict__ W,
                        const float* __restrict__ pos) {
  __shared__ __align__(16) float xs[8 * PD];
  __shared__ __align__(16) float ws[64][129];
  int tid = threadIdx.x;
  int r0 = blockIdx.x * 8;
  // gather 8 patch rows (256 elems each)
  for (int idx = tid; idx < 8 * PD; idx += 128) {
    int rr = idx >> 8, j = idx & 255;
    int r = r0 + rr, b = r / N, n = r % N;
    int gy = n / G, gx = n % G, py = j >> 4, px = j & 15;
    xs[rr * PD + j] = x[(b * IMG + gy * PP + py) * IMG + gx * PP + px];
  }
  float acc[8];
  #pragma unroll
  for (int r = 0; r < 8; r++) acc[r] = NEG;
  mm_core<PD>(xs, ws, W, 0, acc, tid);
  #pragma unroll
  for (int r = 0; r < 8; r++) {
    int rr = r0 + r;
    g_x[rr * D + tid] = acc[r] + pos[(rr % N) * D + tid];
  }
}

// ---------------- QKV: q = trop(x,Wq); k,v = trop(x,W) - rowmax(x) ----------------
__global__ void k_qkv(const float* __restrict__ Wq, const float* __restrict__ Wk,
                      const float* __restrict__ Wv) {
  __shared__ __align__(16) float xs[8 * D];
  __shared__ __align__(16) float ws[64][129];
  __shared__ float rmx[8];
  int tid = threadIdx.x;
  int r0 = blockIdx.x * 8;
  const float* W = (blockIdx.y == 0) ? Wq : ((blockIdx.y == 1) ? Wk : Wv);
  float* out = (blockIdx.y == 0) ? g_q : ((blockIdx.y == 1) ? g_k : g_v);
  for (int idx = tid; idx < 8 * D; idx += 128) xs[idx] = g_x[r0 * D + idx];
  __syncthreads();
  if (tid < 8) {
    float m = NEG;
    for (int j = 0; j < D; j++) m = fmaxf(m, xs[tid * D + j]);
    rmx[tid] = m;
  }
  float acc[8];
  #pragma unroll
  for (int r = 0; r < 8; r++) acc[r] = NEG;
  mm_core<D>(xs, ws, W, 0, acc, tid);   // core's syncs make rmx visible
  bool sub = (blockIdx.y != 0);
  #pragma unroll
  for (int r = 0; r < 8; r++)
    out[(r0 + r) * D + tid] = sub ? (acc[r] - rmx[r]) : acc[r];
}

// ---------------- fused tropical attention + pnorm + residual ----------------
// O'[b,i,d] = max_j( max_e(Q[i,e]+K'[j,e]) + V'[j,d] );  x = max(x, O' - max_d O')
__global__ void k_attn() {
  __shared__ __align__(16) float Qs[8][132];
  __shared__ __align__(16) float Ks[16][132];
  __shared__ __align__(16) float Vs[16][132];
  __shared__ float Ss[8][17];
  int tid = threadIdx.x;
  int b = blockIdx.y, i0 = blockIdx.x * 8;
  int ii = tid >> 4, dg = tid & 15;

  for (int idx = tid; idx < 8 * D; idx += 128) {
    int rr = idx >> 7, c = idx & 127;
    int i = i0 + rr;
    Qs[rr][c] = (i < N) ? g_q[(b * N + i) * D + c] : 0.f;
  }
  float acc[8];
  #pragma unroll
  for (int t = 0; t < 8; t++) acc[t] = NEG;

  for (int j0 = 0; j0 < N; j0 += 16) {
    __syncthreads();
    for (int idx = tid; idx < 16 * D; idx += 128) {
      int rr = idx >> 7, c = idx & 127;
      int j = j0 + rr;
      bool ok = (j < N);
      Ks[rr][c] = ok ? g_k[(b * N + j) * D + c] : NEG;
      Vs[rr][c] = ok ? g_v[(b * N + j) * D + c] : 0.f;
    }
    __syncthreads();
    // S[ii][dg] = max_e(Q + K) with 4 independent max chains
    float s0 = NEG, s1 = NEG, s2 = NEG, s3 = NEG;
    #pragma unroll 8
    for (int e = 0; e < D; e += 4) {
      float4 qv = *reinterpret_cast<const float4*>(&Qs[ii][e]);
      float4 kv = *reinterpret_cast<const float4*>(&Ks[dg][e]);
      s0 = fmaxf(s0, qv.x + kv.x);
      s1 = fmaxf(s1, qv.y + kv.y);
      s2 = fmaxf(s2, qv.z + kv.z);
      s3 = fmaxf(s3, qv.w + kv.w);
    }
    Ss[ii][dg] = fmaxf(fmaxf(s0, s1), fmaxf(s2, s3));
    __syncthreads();
    // O accumulate: thread owns (ii, d = dg*8 .. dg*8+7)
    #pragma unroll
    for (int jj = 0; jj < 16; jj++) {
      float sv = Ss[ii][jj];
      float4 v0 = *reinterpret_cast<const float4*>(&Vs[jj][dg * 8]);
      float4 v1 = *reinterpret_cast<const float4*>(&Vs[jj][dg * 8 + 4]);
      acc[0] = fmaxf(acc[0], sv + v0.x);
      acc[1] = fmaxf(acc[1], sv + v0.y);
      acc[2] = fmaxf(acc[2], sv + v0.z);
      acc[3] = fmaxf(acc[3], sv + v0.w);
      acc[4] = fmaxf(acc[4], sv + v1.x);
      acc[5] = fmaxf(acc[5], sv + v1.y);
      acc[6] = fmaxf(acc[6], sv + v1.z);
      acc[7] = fmaxf(acc[7], sv + v1.w);
    }
  }
  // rowmax over d: local max then reduce over the 16-lane dg group
  float m = fmaxf(fmaxf(fmaxf(acc[0], acc[1]), fmaxf(acc[2], acc[3])),
                  fmaxf(fmaxf(acc[4], acc[5]), fmaxf(acc[6], acc[7])));
  #pragma unroll
  for (int o = 8; o > 0; o >>= 1) m = fmaxf(m, __shfl_xor_sync(0xffffffffu, m, o));
  int i = i0 + ii;
  if (i < N) {
    float* xp = &g_x[(b * N + i) * D + dg * 8];
    #pragma unroll
    for (int t = 0; t < 8; t++) xp[t] = fmaxf(xp[t], acc[t] - m);
  }
}

// ---------------- FF1: h1 = max(trop(x,W1) - rowmax(x), tau) ----------------
__global__ void k_ff1(const float* __restrict__ W, const float* __restrict__ tau) {
  __shared__ __align__(16) float xs[8 * D];
  __shared__ __align__(16) float ws[64][129];
  __shared__ float rmx[8];
  int tid = threadIdx.x;
  int r0 = blockIdx.x * 8, cb = blockIdx.y * 128;
  for (int idx = tid; idx < 8 * D; idx += 128) xs[idx] = g_x[r0 * D + idx];
  __syncthreads();
  if (tid < 8) {
    float m = NEG;
    for (int j = 0; j < D; j++) m = fmaxf(m, xs[tid * D + j]);
    rmx[tid] = m;
  }
  float acc[8];
  #pragma unroll
  for (int r = 0; r < 8; r++) acc[r] = NEG;
  mm_core<D>(xs, ws, W, cb, acc, tid);
  float tv = tau[0];
  #pragma unroll
  for (int r = 0; r < 8; r++)
    g_h1[(r0 + r) * DFF + cb + tid] = fmaxf(acc[r] - rmx[r], tv);
}

// ---------------- FF2: x = max(x, trop(h1,W2) - rowmax_out) ----------------
__global__ void k_ff2(const float* __restrict__ W) {
  __shared__ __align__(16) float xs[8 * DFF];
  __shared__ __align__(16) float ws[64][129];
  __shared__ float part[8][4];
  int tid = threadIdx.x;
  int r0 = blockIdx.x * 8;
  for (int idx = tid; idx < 8 * DFF; idx += 128) xs[idx] = g_h1[r0 * DFF + idx];
  float acc[8];
  #pragma unroll
  for (int r = 0; r < 8; r++) acc[r] = NEG;
  mm_core<DFF>(xs, ws, W, 0, acc, tid);
  int lane = tid & 31, wid = tid >> 5;
  #pragma unroll
  for (int r = 0; r < 8; r++) {
    float v = acc[r];
    #pragma unroll
    for (int o = 16; o > 0; o >>= 1) v = fmaxf(v, __shfl_xor_sync(0xffffffffu, v, o));
    if (lane == 0) part[r][wid] = v;
  }
  __syncthreads();
  #pragma unroll
  for (int r = 0; r < 8; r++) {
    float rm = fmaxf(fmaxf(part[r][0], part[r][1]), fmaxf(part[r][2], part[r][3]));
    int o_ = (r0 + r) * D + tid;
    g_x[o_] = fmaxf(g_x[o_], acc[r] - rm);
  }
}

// ---------------- pool over patches ----------------
__global__ void k_pool() {
  int b = blockIdx.x, d = threadIdx.x;
  float m0 = NEG, m1 = NEG;
  for (int n = 0; n < N; n += 2) {
    m0 = fmaxf(m0, g_x[(b * N + n) * D + d]);
    m1 = fmaxf(m1, g_x[(b * N + n + 1) * D + d]);
  }
  g_pooled[b * D + d] = fmaxf(m0, m1);
}

// ---------------- head: trop(pooled, head_W) * logit_scale ----------------
__global__ void k_head(const float* __restrict__ W, const float* __restrict__ ls,
                       float* __restrict__ out) {
  __shared__ float ps[D];
  int b = blockIdx.y, tid = threadIdx.x;
  int c = blockIdx.x * 128 + tid;
  ps[tid] = g_pooled[b * D + tid];
  __syncthreads();
  if (c < C) {
    const float4* wr = reinterpret_cast<const float4*>(W + c * D);
    float a0 = NEG, a1 = NEG, a2 = NEG, a3 = NEG;
    #pragma unroll 8
    for (int dd = 0; dd < D / 4; dd++) {
      float4 wv = wr[dd];
      a0 = fmaxf(a0, ps[dd * 4 + 0] + wv.x);
      a1 = fmaxf(a1, ps[dd * 4 + 1] + wv.y);
      a2 = fmaxf(a2, ps[dd * 4 + 2] + wv.z);
      a3 = fmaxf(a3, ps[dd * 4 + 3] + wv.w);
    }
    out[b * C + c] = fmaxf(fmaxf(a0, a1), fmaxf(a2, a3)) * ls[0];
  }
}

// ---------------- launch ----------------
extern "C" void kernel_launch(void* const* d_in, const int* in_sizes, int n_in,
                              void* d_out, int out_size) {
  const float* x      = (const float*)d_in[0];
  const float* embedW = (const float*)d_in[1];
  const float* pos    = (const float*)d_in[2];
  const float* qW[2]  = {(const float*)d_in[3], (const float*)d_in[9]};
  const float* kW[2]  = {(const float*)d_in[4], (const float*)d_in[10]};
  const float* vW[2]  = {(const float*)d_in[5], (const float*)d_in[11]};
  const float* f1W[2] = {(const float*)d_in[6], (const float*)d_in[12]};
  const float* f2W[2] = {(const float*)d_in[7], (const float*)d_in[13]};
  const float* tau[2] = {(const float*)d_in[8], (const float*)d_in[14]};
  const float* headW  = (const float*)d_in[15];
  const float* lscale = (const float*)d_in[16];
  float* out = (float*)d_out;

  k_embed<<<BN / 8, 128>>>(x, embedW, pos);
  for (int l = 0; l < 2; l++) {
    k_qkv<<<dim3(BN / 8, 3), 128>>>(qW[l], kW[l], vW[l]);
    k_attn<<<dim3((N + 7) / 8, B), 128>>>();
    k_ff1<<<dim3(BN / 8, 2), 128>>>(f1W[l], tau[l]);
    k_ff2<<<BN / 8, 128>>>(f2W[l]);
  }
  k_pool<<<B, 128>>>();
  k_head<<<dim3((C + 127) / 128, B), 128>>>(headW, lscale, out);
}

// round 3
// speedup vs baseline: 1.4353x; 1.4353x over previous
#include <cuda_runtime.h>

#define NEG (-1e30f)

constexpr int B = 8, IMG = 224, PP = 16, G = 14;
constexpr int N = 196, PD = 256, D = 128, DFF = 256, C = 1000;
constexpr int NP = 208;
constexpr int R = B * NP;          // 1664 padded rows
constexpr int WSP = 129;

__device__ float g_x[R * D];
__device__ float g_q[R * D];
__device__ float g_k[R * D];
__device__ float g_s[R * 256];
__device__ float g_h1[R * DFF];
__device__ float g_vt[B * D * 256];
__device__ float g_pooled[B * D];

extern __shared__ float smem[];

// ---------------- tropical GEMM core ----------------
// 256 threads: col c = cb + (tid&127), row-group rg = tid>>7 -> rows rg*8..rg*8+7.
// xs: [16][KDIM] staged input rows (smem). ws: [64][WSP] transposed W chunk.
// acc[r] = max_k (xs[row][k] + W[col][k]); cols >= maxcol staged as NEG.
template <int KDIM>
__device__ __forceinline__ void gemm_core(const float* xs, float (*ws)[WSP],
                                          const float* __restrict__ W, int wstride,
                                          int cb, int maxcol, float* acc, int tid) {
  int c = tid & 127, rg = tid >> 7;
  const float* xbase = xs + rg * 8 * KDIM;
  for (int k0 = 0; k0 < KDIM; k0 += 64) {
    __syncthreads();
    #pragma unroll
    for (int it = 0; it < 32; it++) {
      int idx = it * 256 + tid;
      int cc = idx >> 6, kk = idx & 63;      // consecutive kk per lane: coalesced LDG; stride-WSP STS conflict-free
      int col = cb + cc;
      ws[kk][cc] = (col < maxcol) ? W[col * wstride + k0 + kk] : NEG;
    }
    __syncthreads();
    #pragma unroll 8
    for (int kk = 0; kk < 64; kk += 4) {
      float w0 = ws[kk][c], w1 = ws[kk + 1][c];
      float w2 = ws[kk + 2][c], w3 = ws[kk + 3][c];
      #pragma unroll
      for (int r = 0; r < 8; r++) {
        float4 xv = *reinterpret_cast<const float4*>(xbase + r * KDIM + k0 + kk);  // warp broadcast
        float a = acc[r];
        a = fmaxf(a, xv.x + w0);
        a = fmaxf(a, xv.y + w1);
        a = fmaxf(a, xv.z + w2);
        a = fmaxf(a, xv.w + w3);
        acc[r] = a;
      }
    }
  }
}

// rowmax of the 16 staged rows; warp w reduces rows 2w, 2w+1 (16 lanes each).
template <int KDIM>
__device__ __forceinline__ void rowmax16(const float* xs, float* rmx, int tid) {
  int w = tid >> 5, lane = tid & 31;
  int row = 2 * w + (lane >> 4), l = lane & 15;
  float m = NEG;
  #pragma unroll
  for (int t = 0; t < KDIM / 16; t++) m = fmaxf(m, xs[row * KDIM + l + 16 * t]);
  #pragma unroll
  for (int o = 8; o; o >>= 1) m = fmaxf(m, __shfl_xor_sync(0xffffffffu, m, o));
  if (l == 0) rmx[row] = m;
}

// ---------------- embed: patchify + trop_mm + pos ----------------
__global__ __launch_bounds__(256) void k_embed(const float* __restrict__ x,
                                               const float* __restrict__ W,
                                               const float* __restrict__ pos) {
  float* xs = smem;                               // 16*256
  float (*ws)[WSP] = (float (*)[WSP])(smem + 16 * 256);
  int tid = threadIdx.x, r0 = blockIdx.x * 16;
  #pragma unroll
  for (int it = 0; it < 16; it++) {               // row it, elem tid
    int r = r0 + it, b = r / NP, n = r % NP;
    if (n > N - 1) n = N - 1;                     // padded rows duplicate row 195
    int gy = n / G, gx = n % G, py = tid >> 4, px = tid & 15;
    xs[it * 256 + tid] = x[(b * IMG + gy * PP + py) * IMG + gx * PP + px];
  }
  float acc[8];
  #pragma unroll
  for (int r = 0; r < 8; r++) acc[r] = NEG;
  gemm_core<256>(xs, ws, W, 256, 0, 1 << 30, acc, tid);
  int c = tid & 127, rg = tid >> 7;
  #pragma unroll
  for (int r = 0; r < 8; r++) {
    int rr = r0 + rg * 8 + r;
    int n = rr % NP; if (n > N - 1) n = N - 1;
    g_x[rr * D + c] = acc[r] + pos[n * D + c];
  }
}

// ---------------- QKV (y=0: q, y=1: k - rowmax(x), y=2: v - rowmax(x) -> vt) ----------------
__global__ __launch_bounds__(256) void k_qkv(const float* __restrict__ Wq,
                                             const float* __restrict__ Wk,
                                             const float* __restrict__ Wv) {
  float* xs = smem;                               // 16*128
  float (*ws)[WSP] = (float (*)[WSP])(smem + 16 * 128);
  __shared__ float rmx[16];
  int tid = threadIdx.x, r0 = blockIdx.x * 16, y = blockIdx.y;
  for (int idx = tid; idx < 16 * D; idx += 256) xs[idx] = g_x[r0 * D + idx];
  __syncthreads();
  rowmax16<128>(xs, rmx, tid);
  const float* W = (y == 0) ? Wq : ((y == 1) ? Wk : Wv);
  float acc[8];
  #pragma unroll
  for (int r = 0; r < 8; r++) acc[r] = NEG;
  gemm_core<128>(xs, ws, W, 128, 0, 1 << 30, acc, tid);   // core's syncs publish rmx
  int c = tid & 127, rg = tid >> 7;
  if (y == 0) {
    #pragma unroll
    for (int r = 0; r < 8; r++) g_q[(r0 + rg * 8 + r) * D + c] = acc[r];
  } else if (y == 1) {
    #pragma unroll
    for (int r = 0; r < 8; r++) g_k[(r0 + rg * 8 + r) * D + c] = acc[r] - rmx[rg * 8 + r];
  } else {
    int b = r0 / NP;
    #pragma unroll
    for (int r = 0; r < 8; r++) {
      int n = (r0 + rg * 8 + r) % NP;
      g_vt[(b * D + c) * 256 + n] = acc[r] - rmx[rg * 8 + r];
    }
  }
}

// ---------------- scores: S[i][j] = max_e(q[i][e] + k'[j][e]); j>=196 -> NEG ----------------
__global__ __launch_bounds__(256) void k_score() {
  float* xs = smem;
  float (*ws)[WSP] = (float (*)[WSP])(smem + 16 * 128);
  int tid = threadIdx.x, r0 = blockIdx.x * 16, cb = blockIdx.y * 128;
  for (int idx = tid; idx < 16 * D; idx += 256) xs[idx] = g_q[r0 * D + idx];
  int b = r0 / NP;
  float acc[8];
  #pragma unroll
  for (int r = 0; r < 8; r++) acc[r] = NEG;
  gemm_core<128>(xs, ws, g_k + b * NP * D, D, cb, N, acc, tid);
  int c = tid & 127, rg = tid >> 7;
  #pragma unroll
  for (int r = 0; r < 8; r++) g_s[(r0 + rg * 8 + r) * 256 + cb + c] = acc[r];
}

// ---------------- FF1: h = max(trop(x,W1) - rowmax(x), tau) ----------------
__global__ __launch_bounds__(256) void k_ff1(const float* __restrict__ W,
                                             const float* __restrict__ tau) {
  float* xs = smem;
  float (*ws)[WSP] = (float (*)[WSP])(smem + 16 * 128);
  __shared__ float rmx[16];
  int tid = threadIdx.x, r0 = blockIdx.x * 16, cb = blockIdx.y * 128;
  for (int idx = tid; idx < 16 * D; idx += 256) xs[idx] = g_x[r0 * D + idx];
  __syncthreads();
  rowmax16<128>(xs, rmx, tid);
  float acc[8];
  #pragma unroll
  for (int r = 0; r < 8; r++) acc[r] = NEG;
  gemm_core<128>(xs, ws, W, 128, cb, 1 << 30, acc, tid);
  float tv = __ldg(tau);
  int c = tid & 127, rg = tid >> 7;
  #pragma unroll
  for (int r = 0; r < 8; r++)
    g_h1[(r0 + rg * 8 + r) * DFF + cb + c] = fmaxf(acc[r] - rmx[rg * 8 + r], tv);
}

// ---------------- out: o = trop(src, W); x = max(x, o - rowmax_d(o)) ----------------
// mode 0: attention output (src = g_s, W = g_vt per-batch)
// mode 1: FF2            (src = g_h1, W = Wext)
__global__ __launch_bounds__(256) void k_out(const float* __restrict__ Wext, int mode) {
  float* xs = smem;                               // 16*256
  float (*ws)[WSP] = (float (*)[WSP])(smem + 16 * 256);
  __shared__ float part[16][4];
  int tid = threadIdx.x, r0 = blockIdx.x * 16;
  const float* src = mode ? (const float*)g_h1 : (const float*)g_s;
  const float* W = mode ? Wext : (const float*)g_vt + (r0 / NP) * D * 256;
  for (int idx = tid; idx < 16 * 256; idx += 256) xs[idx] = src[r0 * 256 + idx];
  float acc[8];
  #pragma unroll
  for (int r = 0; r < 8; r++) acc[r] = NEG;
  gemm_core<256>(xs, ws, W, 256, 0, 1 << 30, acc, tid);
  int c = tid & 127, rg = tid >> 7, wq = (tid >> 5) & 3;
  #pragma unroll
  for (int r = 0; r < 8; r++) {
    float v = acc[r];
    #pragma unroll
    for (int o = 16; o; o >>= 1) v = fmaxf(v, __shfl_xor_sync(0xffffffffu, v, o));
    if ((tid & 31) == 0) part[rg * 8 + r][wq] = v;
  }
  __syncthreads();
  #pragma unroll
  for (int r = 0; r < 8; r++) {
    float rm = fmaxf(fmaxf(part[rg * 8 + r][0], part[rg * 8 + r][1]),
                     fmaxf(part[rg * 8 + r][2], part[rg * 8 + r][3]));
    int o_ = (r0 + rg * 8 + r) * D + c;
    g_x[o_] = fmaxf(g_x[o_], acc[r] - rm);
  }
}

// ---------------- pool + head ----------------
__global__ void k_pool() {
  int b = blockIdx.x, d = threadIdx.x;
  float m0 = NEG, m1 = NEG;
  for (int n = 0; n < N - 1; n += 2) {
    m0 = fmaxf(m0, g_x[(b * NP + n) * D + d]);
    m1 = fmaxf(m1, g_x[(b * NP + n + 1) * D + d]);
  }
  g_pooled[b * D + d] = fmaxf(m0, m1);
}

__global__ void k_head(const float* __restrict__ W, const float* __restrict__ ls,
                       float* __restrict__ out) {
  __shared__ float ps[D];
  int b = blockIdx.y, tid = threadIdx.x;
  int c = blockIdx.x * 128 + tid;
  ps[tid] = g_pooled[b * D + tid];
  __syncthreads();
  if (c < C) {
    const float4* wr = reinterpret_cast<const float4*>(W + c * D);
    float a0 = NEG, a1 = NEG, a2 = NEG, a3 = NEG;
    #pragma unroll 8
    for (int dd = 0; dd < D / 4; dd++) {
      float4 wv = wr[dd];
      a0 = fmaxf(a0, ps[dd * 4 + 0] + wv.x);
      a1 = fmaxf(a1, ps[dd * 4 + 1] + wv.y);
      a2 = fmaxf(a2, ps[dd * 4 + 2] + wv.z);
      a3 = fmaxf(a3, ps[dd * 4 + 3] + wv.w);
    }
    out[b * C + c] = fmaxf(fmaxf(a0, a1), fmaxf(a2, a3)) * ls[0];
  }
}

// ---------------- launch ----------------
extern "C" void kernel_launch(void* const* d_in, const int* in_sizes, int n_in,
                              void* d_out, int out_size) {
  const float* x      = (const float*)d_in[0];
  const float* embedW = (const float*)d_in[1];
  const float* pos    = (const float*)d_in[2];
  const float* qW[2]  = {(const float*)d_in[3], (const float*)d_in[9]};
  const float* kW[2]  = {(const float*)d_in[4], (const float*)d_in[10]};
  const float* vW[2]  = {(const float*)d_in[5], (const float*)d_in[11]};
  const float* f1W[2] = {(const float*)d_in[6], (const float*)d_in[12]};
  const float* f2W[2] = {(const float*)d_in[7], (const float*)d_in[13]};
  const float* tau[2] = {(const float*)d_in[8], (const float*)d_in[14]};
  const float* headW  = (const float*)d_in[15];
  const float* lscale = (const float*)d_in[16];
  float* out = (float*)d_out;

  const int S128 = (16 * 128 + 64 * WSP) * 4;   // 41216 B
  const int S256 = (16 * 256 + 64 * WSP) * 4;   // 49408 B
  static bool attr_done = false;
  if (!attr_done) {
    cudaFuncSetAttribute(k_embed, cudaFuncAttributeMaxDynamicSharedMemorySize, S256);
    cudaFuncSetAttribute(k_qkv,   cudaFuncAttributeMaxDynamicSharedMemorySize, S128);
    cudaFuncSetAttribute(k_score, cudaFuncAttributeMaxDynamicSharedMemorySize, S128);
    cudaFuncSetAttribute(k_ff1,   cudaFuncAttributeMaxDynamicSharedMemorySize, S128);
    cudaFuncSetAttribute(k_out,   cudaFuncAttributeMaxDynamicSharedMemorySize, S256);
    attr_done = true;
  }

  const int RB = R / 16;   // 104 row blocks

  k_embed<<<RB, 256, S256>>>(x, embedW, pos);
  for (int l = 0; l < 2; l++) {
    k_qkv<<<dim3(RB, 3), 256, S128>>>(qW[l], kW[l], vW[l]);
    k_score<<<dim3(RB, 2), 256, S128>>>();
    k_out<<<RB, 256, S256>>>(nullptr, 0);        // attention output + pnorm + residual
    k_ff1<<<dim3(RB, 2), 256, S128>>>(f1W[l], tau[l]);
    k_out<<<RB, 256, S256>>>(f2W[l], 1);         // FF2 + pnorm + residual
  }
  k_pool<<<B, 128>>>();
  k_head<<<dim3((C + 127) / 128, B), 128>>>(headW, lscale, out);
}

// round 7
// speedup vs baseline: 1.9270x; 1.3426x over previous
#include <cuda_runtime.h>

#define NEG (-1e30f)

constexpr int Bz = 8, IMG = 224, G = 14;
constexpr int N = 196, D = 128, NP = 208;
constexpr int R = Bz * NP;          // 1664 padded rows
constexpr int RB = R / 4;           // 416 row blocks

// ---------------- scratch (device globals; zero-init, no allocation) ----------------
__device__ float  g_x[R * D];
__device__ float  g_q[R * D];
__device__ float  g_s[R * 256];
__device__ float  g_h1[R * 256];
__device__ float4 g_k4[Bz * 32 * NP];     // [b][e4][j]  .xyzw = k'[j][4e4..4e4+3]
__device__ float4 g_vt4[Bz * 64 * 128];   // [b][j4][d]  .xyzw = v'[4j4..4j4+3][d]; j4>=52 stays 0
__device__ float  g_pooled[Bz * D];
__device__ float4 g_wt[97536];            // all transposed weights, k4-major

// transposed-weight offsets (float4 units) — HOST ONLY; device gets them as args
constexpr int OFF_Q[2]  = {8192, 36864};
constexpr int OFF_K[2]  = {12288, 40960};
constexpr int OFF_V[2]  = {16384, 45056};
constexpr int OFF_F1[2] = {20480, 49152};
constexpr int OFF_F2[2] = {28672, 57344};
constexpr int OFF_HEAD  = 65536;

#define TROP(a, xv, w)                                  \
  {                                                     \
    a = fmaxf(a, (xv).x + (w).x);                       \
    a = fmaxf(a, (xv).y + (w).y);                       \
    a = fmaxf(a, (xv).z + (w).z);                       \
    a = fmaxf(a, (xv).w + (w).w);                       \
  }

// ---------------- one-shot weight transpose into k4-major ----------------
struct SrcPtrs { const float* p[12]; };
__device__ const int c_cols[12] = {128, 128, 128, 128, 256, 128, 128, 128, 128, 256, 128, 1000};
__device__ const int c_Kd[12]   = {256, 128, 128, 128, 128, 256, 128, 128, 128, 128, 256, 128};
__device__ const int c_off[12]  = {0, 8192, 12288, 16384, 20480, 28672, 36864, 40960, 45056, 49152, 57344, 65536};

__global__ void k_trans(SrcPtrs sp) {
  int w = blockIdx.y;
  int cols = c_cols[w], K = c_Kd[w];
  int n4 = cols * (K >> 2);
  int idx = blockIdx.x * 256 + threadIdx.x;
  if (idx >= n4) return;
  int k4 = idx / cols, c = idx - k4 * cols;
  g_wt[c_off[w] + idx] = *(const float4*)(sp.p[w] + c * K + k4 * 4);  // dst coalesced (c fast)
}

// ---------------- embed: patchify + trop_mm + pos ----------------
__global__ __launch_bounds__(128) void k_embed(const float* __restrict__ x,
                                               const float* __restrict__ pos) {
  __shared__ float xs[4 * 256];
  int tid = threadIdx.x, r0 = blockIdx.x * 4;
  int b = r0 / NP;
  #pragma unroll
  for (int it = 0; it < 8; it++) {
    int idx = it * 128 + tid, rr = idx >> 8, j = idx & 255;
    int n = (r0 + rr) % NP; if (n > N - 1) n = N - 1;   // padded rows duplicate 195
    int gy = n / G, gx = n % G, py = j >> 4, px = j & 15;
    xs[idx] = x[(b * IMG + gy * 16 + py) * IMG + gx * 16 + px];
  }
  __syncthreads();
  const float4* xs4 = (const float4*)xs;
  const float4* Wt = g_wt;                  // embed at offset 0, ncols=128
  float a0 = NEG, a1 = NEG, a2 = NEG, a3 = NEG;
  #pragma unroll 4
  for (int k4 = 0; k4 < 64; k4++) {
    float4 w = Wt[k4 * 128 + tid];
    float4 x0 = xs4[k4], x1 = xs4[64 + k4], x2 = xs4[128 + k4], x3 = xs4[192 + k4];
    TROP(a0, x0, w); TROP(a1, x1, w); TROP(a2, x2, w); TROP(a3, x3, w);
  }
  float acc[4] = {a0, a1, a2, a3};
  #pragma unroll
  for (int r = 0; r < 4; r++) {
    int rr = r0 + r, n = rr % NP; if (n > N - 1) n = N - 1;
    g_x[rr * D + tid] = acc[r] + pos[n * D + tid];
  }
}

// ---------------- QKV (y=0: q, y=1: k-rmx -> g_k4, y=2: v-rmx -> g_vt4) ----------------
__global__ __launch_bounds__(128) void k_qkv(int qoff, int koff, int voff) {
  __shared__ float xs[4 * 128];
  __shared__ float rmx[4];
  int tid = threadIdx.x, r0 = blockIdx.x * 4, y = blockIdx.y;
  int b = r0 / NP;
  #pragma unroll
  for (int it = 0; it < 4; it++) xs[it * 128 + tid] = g_x[(r0 + it) * D + tid];
  __syncthreads();
  {
    int w = tid >> 5, lane = tid & 31;
    float m = fmaxf(fmaxf(xs[w * 128 + lane], xs[w * 128 + lane + 32]),
                    fmaxf(xs[w * 128 + lane + 64], xs[w * 128 + lane + 96]));
    #pragma unroll
    for (int o = 16; o; o >>= 1) m = fmaxf(m, __shfl_xor_sync(~0u, m, o));
    if (lane == 0) rmx[w] = m;
  }
  const float4* Wt = g_wt + (y == 0 ? qoff : (y == 1 ? koff : voff));
  const float4* xs4 = (const float4*)xs;
  float a0 = NEG, a1 = NEG, a2 = NEG, a3 = NEG;
  #pragma unroll 4
  for (int k4 = 0; k4 < 32; k4++) {
    float4 w = Wt[k4 * 128 + tid];
    float4 x0 = xs4[k4], x1 = xs4[32 + k4], x2 = xs4[64 + k4], x3 = xs4[96 + k4];
    TROP(a0, x0, w); TROP(a1, x1, w); TROP(a2, x2, w); TROP(a3, x3, w);
  }
  __syncthreads();                                     // publish rmx
  float acc[4] = {a0, a1, a2, a3};
  if (y == 0) {
    #pragma unroll
    for (int r = 0; r < 4; r++) g_q[(r0 + r) * D + tid] = acc[r];
  } else if (y == 1) {
    #pragma unroll
    for (int r = 0; r < 4; r++) {
      int n = (r0 + r) % NP;
      ((float*)g_k4)[((b * 32 + (tid >> 2)) * NP + n) * 4 + (tid & 3)] = acc[r] - rmx[r];
    }
  } else {
    #pragma unroll
    for (int r = 0; r < 4; r++) {
      int n = (r0 + r) % NP;
      ((float*)g_vt4)[((b * 64 + (n >> 2)) * 128 + tid) * 4 + (n & 3)] = acc[r] - rmx[r];
    }
  }
}

// ---------------- scores: S[i][j] = max_e(q[i][e] + k'[j][e]); j>=196 -> NEG ----------------
__global__ __launch_bounds__(128) void k_score() {
  __shared__ float xs[4 * 128];
  int tid = threadIdx.x, r0 = blockIdx.x * 4, j = blockIdx.y * 128 + tid;
  int b = r0 / NP;
  #pragma unroll
  for (int it = 0; it < 4; it++) xs[it * 128 + tid] = g_q[(r0 + it) * D + tid];
  __syncthreads();
  float a0 = NEG, a1 = NEG, a2 = NEG, a3 = NEG;
  if (j < N) {
    const float4* Kt = g_k4 + b * 32 * NP;
    const float4* xs4 = (const float4*)xs;
    #pragma unroll 4
    for (int k4 = 0; k4 < 32; k4++) {
      float4 w = Kt[k4 * NP + j];
      float4 x0 = xs4[k4], x1 = xs4[32 + k4], x2 = xs4[64 + k4], x3 = xs4[96 + k4];
      TROP(a0, x0, w); TROP(a1, x1, w); TROP(a2, x2, w); TROP(a3, x3, w);
    }
  }
  g_s[(r0 + 0) * 256 + j] = a0;
  g_s[(r0 + 1) * 256 + j] = a1;
  g_s[(r0 + 2) * 256 + j] = a2;
  g_s[(r0 + 3) * 256 + j] = a3;
}

// ---------------- FF1: h = max(trop(x,W1) - rmx, tau) ----------------
__global__ __launch_bounds__(128) void k_ff1(int f1off, const float* __restrict__ tau) {
  __shared__ float xs[4 * 128];
  __shared__ float rmx[4];
  int tid = threadIdx.x, r0 = blockIdx.x * 4, cb = blockIdx.y * 128;
  #pragma unroll
  for (int it = 0; it < 4; it++) xs[it * 128 + tid] = g_x[(r0 + it) * D + tid];
  __syncthreads();
  {
    int w = tid >> 5, lane = tid & 31;
    float m = fmaxf(fmaxf(xs[w * 128 + lane], xs[w * 128 + lane + 32]),
                    fmaxf(xs[w * 128 + lane + 64], xs[w * 128 + lane + 96]));
    #pragma unroll
    for (int o = 16; o; o >>= 1) m = fmaxf(m, __shfl_xor_sync(~0u, m, o));
    if (lane == 0) rmx[w] = m;
  }
  const float4* Wt = g_wt + f1off;
  const float4* xs4 = (const float4*)xs;
  float a0 = NEG, a1 = NEG, a2 = NEG, a3 = NEG;
  #pragma unroll 4
  for (int k4 = 0; k4 < 32; k4++) {
    float4 w = Wt[k4 * 256 + cb + tid];
    float4 x0 = xs4[k4], x1 = xs4[32 + k4], x2 = xs4[64 + k4], x3 = xs4[96 + k4];
    TROP(a0, x0, w); TROP(a1, x1, w); TROP(a2, x2, w); TROP(a3, x3, w);
  }
  __syncthreads();                                     // publish rmx
  float acc[4] = {a0, a1, a2, a3};
  float tv = __ldg(tau);
  #pragma unroll
  for (int r = 0; r < 4; r++)
    g_h1[(r0 + r) * 256 + cb + tid] = fmaxf(acc[r] - rmx[r], tv);
}

// ---------------- out: o = trop(src, W); x = max(x, o - rowmax_d(o)) ----------------
// mode 0: attention output (src=g_s, W=g_vt4 per batch); mode 1: FF2 (src=g_h1, W=g_wt+wtoff)
__global__ __launch_bounds__(128) void k_out(int wtoff, int mode) {
  __shared__ float xs[4 * 256];
  __shared__ float part[4][4];
  int tid = threadIdx.x, r0 = blockIdx.x * 4, b = r0 / NP;
  const float* src = mode ? g_h1 : g_s;
  #pragma unroll
  for (int it = 0; it < 8; it++) xs[it * 128 + tid] = src[r0 * 256 + it * 128 + tid];
  __syncthreads();
  const float4* Wt = mode ? (g_wt + wtoff) : (g_vt4 + b * 64 * 128);
  const float4* xs4 = (const float4*)xs;
  float a0 = NEG, a1 = NEG, a2 = NEG, a3 = NEG;
  #pragma unroll 4
  for (int k4 = 0; k4 < 64; k4++) {
    float4 w = Wt[k4 * 128 + tid];
    float4 x0 = xs4[k4], x1 = xs4[64 + k4], x2 = xs4[128 + k4], x3 = xs4[192 + k4];
    TROP(a0, x0, w); TROP(a1, x1, w); TROP(a2, x2, w); TROP(a3, x3, w);
  }
  float acc[4] = {a0, a1, a2, a3};
  int w = tid >> 5, lane = tid & 31;
  #pragma unroll
  for (int r = 0; r < 4; r++) {
    float v = acc[r];
    #pragma unroll
    for (int o = 16; o; o >>= 1) v = fmaxf(v, __shfl_xor_sync(~0u, v, o));
    if (lane == 0) part[r][w] = v;
  }
  __syncthreads();
  #pragma unroll
  for (int r = 0; r < 4; r++) {
    float rm = fmaxf(fmaxf(part[r][0], part[r][1]), fmaxf(part[r][2], part[r][3]));
    int o_ = (r0 + r) * D + tid;
    g_x[o_] = fmaxf(g_x[o_], acc[r] - rm);
  }
}

// ---------------- pool + head ----------------
__global__ void k_pool() {
  __shared__ float pp[4][128];
  int b = blockIdx.x, tid = threadIdx.x, d = tid & 127, gp = tid >> 7;
  float m = NEG;
  for (int n = gp; n < N; n += 4) m = fmaxf(m, g_x[(b * NP + n) * D + d]);
  pp[gp][d] = m;
  __syncthreads();
  if (gp == 0)
    g_pooled[b * D + d] = fmaxf(fmaxf(pp[0][d], pp[1][d]), fmaxf(pp[2][d], pp[3][d]));
}

__global__ __launch_bounds__(128) void k_head(int hoff, const float* __restrict__ ls,
                                              float* __restrict__ out) {
  __shared__ float ps[128];
  int b = blockIdx.y, tid = threadIdx.x, c = blockIdx.x * 128 + tid;
  ps[tid] = g_pooled[b * D + tid];
  __syncthreads();
  if (c < 1000) {
    const float4* Wt = g_wt + hoff;
    const float4* ps4 = (const float4*)ps;
    float a0 = NEG, a1 = NEG, a2 = NEG, a3 = NEG;
    #pragma unroll 4
    for (int k4 = 0; k4 < 32; k4++) {
      float4 w = Wt[k4 * 1000 + c];
      float4 xv = ps4[k4];
      a0 = fmaxf(a0, xv.x + w.x);
      a1 = fmaxf(a1, xv.y + w.y);
      a2 = fmaxf(a2, xv.z + w.z);
      a3 = fmaxf(a3, xv.w + w.w);
    }
    out[b * 1000 + c] = fmaxf(fmaxf(a0, a1), fmaxf(a2, a3)) * __ldg(ls);
  }
}

// ---------------- launch ----------------
extern "C" void kernel_launch(void* const* d_in, const int* in_sizes, int n_in,
                              void* d_out, int out_size) {
  const float* x      = (const float*)d_in[0];
  const float* pos    = (const float*)d_in[2];
  const float* tau[2] = {(const float*)d_in[8], (const float*)d_in[14]};
  const float* lscale = (const float*)d_in[16];
  float* out = (float*)d_out;

  SrcPtrs sp = {{(const float*)d_in[1],
                 (const float*)d_in[3], (const float*)d_in[4], (const float*)d_in[5],
                 (const float*)d_in[6], (const float*)d_in[7],
                 (const float*)d_in[9], (const float*)d_in[10], (const float*)d_in[11],
                 (const float*)d_in[12], (const float*)d_in[13],
                 (const float*)d_in[15]}};

  k_trans<<<dim3(125, 12), 256>>>(sp);
  k_embed<<<RB, 128>>>(x, pos);
  for (int l = 0; l < 2; l++) {
    k_qkv<<<dim3(RB, 3), 128>>>(OFF_Q[l], OFF_K[l], OFF_V[l]);
    k_score<<<dim3(RB, 2), 128>>>();
    k_out<<<RB, 128>>>(0, 0);            // attention output + pnorm + residual
    k_ff1<<<dim3(RB, 2), 128>>>(OFF_F1[l], tau[l]);
    k_out<<<RB, 128>>>(OFF_F2[l], 1);    // FF2 + pnorm + residual
  }
  k_pool<<<Bz, 512>>>();
  k_head<<<dim3(8, Bz), 128>>>(OFF_HEAD, lscale, out);
}